// round 15
// baseline (speedup 1.0000x reference)
#include <cuda_runtime.h>
#include <cstdint>

#define BATCH 8
#define C 256
#define OC2 512
#define H 96
#define W 96
#define HW 9216          // 96*96
#define HP 98
#define PP 9604          // 98*98
#define POUT 256
#define EPS 1e-5f

// ---------------- scratch (static device globals; no allocation) -------------
__device__ float    g_wr[9 * C * OC2];       // conv weights [tap][ic][oc], tf32-rounded
__device__ float    g_xt[BATCH * C * HW];    // x, tf32-rounded (offconv B operand)
__device__ unsigned g_wpt_hi[C * POUT];      // pointwise weights tf32-hi [c][o]
__device__ unsigned g_wpt_lo[C * POUT];      // pointwise weights tf32-lo [c][o]
__device__ float    g_off[(size_t)BATCH * OC2 * PP];
__device__ float    g_xd[BATCH * C * HW];
__device__ float    g_sums[2 * C];
__device__ float    g_scale[C];
__device__ float    g_shift[C];

__device__ __forceinline__ unsigned f2tf32(float f) {
    unsigned u;
    asm("cvt.rna.tf32.f32 %0, %1;" : "=r"(u) : "f"(f));
    return u;
}
__device__ __forceinline__ void cp16(unsigned dst, const void* src) {
    asm volatile("cp.async.cg.shared.global [%0], [%1], 16;"
                 :: "r"(dst), "l"(src));
}
__device__ __forceinline__ void cp4z(unsigned dst, const void* src, int srcsz) {
    asm volatile("cp.async.ca.shared.global [%0], [%1], 4, %2;"
                 :: "r"(dst), "l"(src), "r"(srcsz));
}

// ---------------- kernel 0: weight prep + stats re-zero ----------------------
__global__ void k_prep(const float* __restrict__ w, const float* __restrict__ wpw) {
    int i = blockIdx.x * 256 + threadIdx.x;
    if (i < 2 * C) g_sums[i] = 0.f;          // re-zero every call (graph replay)
    if (i < OC2 * C * 9) {
        int oc  = i / (C * 9);
        int r   = i - oc * (C * 9);
        int ic  = r / 9;
        int tap = r - ic * 9;
        g_wr[(tap * C + ic) * OC2 + oc] = __uint_as_float(f2tf32(w[i]));
    }
    if (i < POUT * C) {
        int o = i >> 8;      // POUT == 256
        int c = i & 255;     // C == 256
        float v = wpw[i];    // [o][c]
        unsigned hi = f2tf32(v);
        float lo = v - __uint_as_float(hi);
        g_wpt_hi[c * POUT + o] = hi;
        g_wpt_lo[c * POUT + o] = f2tf32(lo);
    }
}

// ---------------- kernel 0b: pre-round x to tf32 -----------------------------
__global__ void k_prepx(const float* __restrict__ x) {
    int i = blockIdx.x * 256 + threadIdx.x;
    g_xt[i] = __uint_as_float(f2tf32(x[i]));
}

// ---------------- kernel 1: offset conv, TF32 mma.sync, BK=64 double-buffer --
// Block tile 256(oc) x 128(p). 256 threads = 8 warps (4 oc x 2 p), warp 64x64.
#define ASTR 264          // 256+8 floats
#define BSTR 136          // 128+8 floats
#define STG  (64 * ASTR + 64 * BSTR)   // floats per stage = 25600 (102.4 KB)
#define NSTG 2
#define NITER 36                        // 9 taps * 4 k-chunks of 64
__global__ __launch_bounds__(256, 1) void k_offconv() {
    extern __shared__ float sh[];      // NSTG * STG floats

    const int t    = threadIdx.x;
    const int warp = t >> 5;
    const int lane = t & 31;
    const int gr   = lane >> 2;
    const int gc   = lane & 3;
    const int w_oc = (warp >> 1) * 64;   // 0,64,128,192
    const int w_p  = (warp & 1) * 64;    // 0,64

    const int b   = blockIdx.z;
    const int oc0 = blockIdx.y * 256;
    const int p0  = blockIdx.x * 128;

    const int ppl = t & 127;
    const int kb  = t >> 7;             // 0..1
    const int P   = p0 + ppl;
    const bool pv = (P < PP);
    const int yy  = P / HP;
    const int xx  = P - yy * HP;

    float acc[4][8][4];
#pragma unroll
    for (int i = 0; i < 4; i++)
#pragma unroll
        for (int j = 0; j < 8; j++)
#pragma unroll
            for (int r = 0; r < 4; r++) acc[i][j][r] = 0.f;

    const float* xb = g_xt + (size_t)b * C * HW;

    auto issue = [&](int j) {
        const int s   = j & (NSTG - 1);
        const int tap = j >> 2;
        const int ic0 = (j & 3) << 6;
        float* stA = sh + s * STG;
        float* stB = stA + 64 * ASTR;
        {
            const float* wt = g_wr + (size_t)(tap * C + ic0) * OC2 + oc0;
#pragma unroll
            for (int u = 0; u < 16; ++u) {
                int c  = t + 256 * u;
                int ar = c >> 6;
                int ac = (c & 63) << 2;
                cp16((unsigned)__cvta_generic_to_shared(stA + ar * ASTR + ac),
                     wt + (size_t)ar * OC2 + ac);
            }
        }
        {
            const int ky = tap / 3;
            const int kx = tap - ky * 3;
            const int Y  = yy + ky - 2;
            const int X  = xx + kx - 2;
            const bool inb = pv && ((unsigned)Y < (unsigned)H) && ((unsigned)X < (unsigned)W);
            const int sp = inb ? (Y * W + X) : 0;
            const int sz = inb ? 4 : 0;
            const float* xc = xb + (size_t)ic0 * HW + sp;
#pragma unroll
            for (int u = 0; u < 32; ++u) {
                int kk = kb + 2 * u;
                cp4z((unsigned)__cvta_generic_to_shared(stB + kk * BSTR + ppl),
                     xc + (size_t)kk * HW, sz);
            }
        }
        asm volatile("cp.async.commit_group;" ::: "memory");
    };

    issue(0);

#pragma unroll 1
    for (int j = 0; j < NITER; ++j) {
        const int s = j & (NSTG - 1);
        asm volatile("cp.async.wait_group 0;" ::: "memory");   // stage j landed
        __syncthreads();
        if (j + 1 < NITER) issue(j + 1);

        const float* stA = sh + s * STG;
        const float* stB = stA + 64 * ASTR;

#pragma unroll
        for (int ks = 0; ks < 64; ks += 8) {
            unsigned af[4][4], bf[8][2];
#pragma unroll
            for (int mi = 0; mi < 4; ++mi) {
                int oc = w_oc + mi * 16 + gr;
                af[mi][0] = __float_as_uint(stA[(ks + gc)     * ASTR + oc]);
                af[mi][1] = __float_as_uint(stA[(ks + gc)     * ASTR + oc + 8]);
                af[mi][2] = __float_as_uint(stA[(ks + gc + 4) * ASTR + oc]);
                af[mi][3] = __float_as_uint(stA[(ks + gc + 4) * ASTR + oc + 8]);
            }
#pragma unroll
            for (int nj = 0; nj < 8; ++nj) {
                int pc = w_p + nj * 8 + gr;
                bf[nj][0] = __float_as_uint(stB[(ks + gc)     * BSTR + pc]);
                bf[nj][1] = __float_as_uint(stB[(ks + gc + 4) * BSTR + pc]);
            }
#pragma unroll
            for (int mi = 0; mi < 4; ++mi)
#pragma unroll
                for (int nj = 0; nj < 8; ++nj)
                    asm volatile(
                        "mma.sync.aligned.m16n8k8.row.col.f32.tf32.tf32.f32 "
                        "{%0,%1,%2,%3}, {%4,%5,%6,%7}, {%8,%9}, {%0,%1,%2,%3};"
                        : "+f"(acc[mi][nj][0]), "+f"(acc[mi][nj][1]),
                          "+f"(acc[mi][nj][2]), "+f"(acc[mi][nj][3])
                        : "r"(af[mi][0]), "r"(af[mi][1]), "r"(af[mi][2]), "r"(af[mi][3]),
                          "r"(bf[nj][0]), "r"(bf[nj][1]));
        }
    }

#pragma unroll
    for (int mi = 0; mi < 4; ++mi) {
#pragma unroll
        for (int nj = 0; nj < 8; ++nj) {
            int row0 = oc0 + w_oc + mi * 16 + gr;
            int col  = p0 + w_p + nj * 8 + 2 * gc;
            float* d0 = g_off + ((size_t)b * OC2 + row0) * PP + col;
            float* d1 = d0 + 8 * PP;
            if (col + 1 < PP) {
                *(float2*)d0 = make_float2(acc[mi][nj][0], acc[mi][nj][1]);
                *(float2*)d1 = make_float2(acc[mi][nj][2], acc[mi][nj][3]);
            } else if (col < PP) {
                d0[0] = acc[mi][nj][0];
                d1[0] = acc[mi][nj][2];
            }
        }
    }
}

// ---------------- kernel 2: bilinear deform sampling + BN partial sums -------
__global__ __launch_bounds__(256) void k_sample(const float* __restrict__ x) {
    const int bc = blockIdx.x;
    const int b  = bc >> 8;
    const int c  = bc & 255;
    const float* xc = x + (size_t)bc * HW;
    const float* offb = g_off + ((size_t)b * OC2 + 2 * c) * PP;

    float s1 = 0.f, s2 = 0.f;
    for (int i = threadIdx.x; i < HW; i += 256) {
        int iy = i / W;
        int ix = i - iy * W;
        int yy = iy + 1, xx = ix + 1;
        int p2 = 2 * (yy * HP + xx);
        float oy = __ldg(offb + p2);
        float ox = __ldg(offb + p2 + 1);
        float cy = fminf(fmaxf((float)yy + oy, 0.f), 97.f);
        float cx = fminf(fmaxf((float)xx + ox, 0.f), 97.f);
        float fy = floorf(cy), fx = floorf(cx);
        int y0 = (int)fy, x0 = (int)fx;
        int y1 = min(y0 + 1, 97), x1 = min(x0 + 1, 97);
        float dy = cy - fy, dx = cx - fx;
        float v00 = (y0 >= 1 && y0 <= 96 && x0 >= 1 && x0 <= 96) ? __ldg(xc + (y0 - 1) * W + (x0 - 1)) : 0.f;
        float v01 = (y0 >= 1 && y0 <= 96 && x1 >= 1 && x1 <= 96) ? __ldg(xc + (y0 - 1) * W + (x1 - 1)) : 0.f;
        float v10 = (y1 >= 1 && y1 <= 96 && x0 >= 1 && x0 <= 96) ? __ldg(xc + (y1 - 1) * W + (x0 - 1)) : 0.f;
        float v11 = (y1 >= 1 && y1 <= 96 && x1 >= 1 && x1 <= 96) ? __ldg(xc + (y1 - 1) * W + (x1 - 1)) : 0.f;
        float top = v00 + (v01 - v00) * dx;
        float bot = v10 + (v11 - v10) * dx;
        float v   = top + (bot - top) * dy;
        g_xd[(size_t)bc * HW + i] = v;
        s1 += v;
        s2 += v * v;
    }
#pragma unroll
    for (int off = 16; off > 0; off >>= 1) {
        s1 += __shfl_down_sync(0xffffffffu, s1, off);
        s2 += __shfl_down_sync(0xffffffffu, s2, off);
    }
    __shared__ float r1[8], r2[8];
    int lane = threadIdx.x & 31, wid = threadIdx.x >> 5;
    if (lane == 0) { r1[wid] = s1; r2[wid] = s2; }
    __syncthreads();
    if (threadIdx.x == 0) {
        float a = 0.f, q = 0.f;
#pragma unroll
        for (int i = 0; i < 8; i++) { a += r1[i]; q += r2[i]; }
        atomicAdd(&g_sums[2 * c], a);
        atomicAdd(&g_sums[2 * c + 1], q);
    }
}

// ---------------- kernel 3: BN scale/shift from batch stats ------------------
__global__ void k_bn(const float* __restrict__ gamma, const float* __restrict__ beta) {
    int c = threadIdx.x;
    const float invn = 1.f / (float)(BATCH * HW);
    float mean = g_sums[2 * c] * invn;
    float var  = g_sums[2 * c + 1] * invn - mean * mean;
    float inv  = rsqrtf(var + EPS);
    float sc   = gamma[c] * inv;
    g_scale[c] = sc;
    g_shift[c] = fmaf(-mean, sc, beta[c]);
}

// ---------------- kernel 4: pointwise 1x1, 3xTF32 mma, pipelined (race-free) -
// Block tile 128(o) x 128(p), BK=32, 8 k-iters. 256 threads = 8 warps (2x4).
// Order per iter: store-B(j) -> wait_group 0 -> sync -> issueA(j+1) -> loadB(j+1)
// -> compute(j). All cross-buffer reuse is separated by a barrier.
#define PASTR 136
#define PWSTG (32 * PASTR)              // words per plane per buffer = 4352
__global__ __launch_bounds__(256) void k_pw(float* __restrict__ out) {
    extern __shared__ unsigned psh[];   // Ah[2] | Al[2] | Bh[2] | Bl[2]
    unsigned* Ah = psh;
    unsigned* Al = psh + 2 * PWSTG;
    unsigned* Bh = psh + 4 * PWSTG;
    unsigned* Bl = psh + 6 * PWSTG;

    const int t    = threadIdx.x;
    const int warp = t >> 5;
    const int lane = t & 31;
    const int gr   = lane >> 2;
    const int gc   = lane & 3;
    const int w_o  = (warp >> 2) * 64;
    const int w_p  = (warp & 3) * 32;

    const int b  = blockIdx.z;
    const int o0 = blockIdx.y * 128;
    const int p0 = blockIdx.x * 128;

    const int cl = t & 127;   // B loader column
    const int kl = t >> 7;    // B loader row base (0..1)

    const float* xb = g_xd + (size_t)b * C * HW;

    float acc[4][4][4];
#pragma unroll
    for (int i = 0; i < 4; i++)
#pragma unroll
        for (int j = 0; j < 4; j++)
#pragma unroll
            for (int r = 0; r < 4; r++) acc[i][j][r] = 0.f;

    // A stage loader: 32 rows x 128 cols, hi+lo, 4x2 cp16 per thread
    auto issueA = [&](int j) {
        const int ic0 = j << 5;
        const unsigned bo = (j & 1) * PWSTG;
        const unsigned* wh = g_wpt_hi + (size_t)ic0 * POUT + o0;
        const unsigned* wl = g_wpt_lo + (size_t)ic0 * POUT + o0;
#pragma unroll
        for (int u = 0; u < 4; ++u) {
            int id = t + 256 * u;        // 0..1023
            int r  = id >> 5;            // 0..31
            int c4 = (id & 31) << 2;     // 0..124
            cp16((unsigned)__cvta_generic_to_shared(Ah + bo + r * PASTR + c4),
                 wh + (size_t)r * POUT + c4);
            cp16((unsigned)__cvta_generic_to_shared(Al + bo + r * PASTR + c4),
                 wl + (size_t)r * POUT + c4);
        }
        asm volatile("cp.async.commit_group;" ::: "memory");
    };
    // B prefetch: 16 raw values into registers
    auto loadB = [&](int j, float* bv) {
        const int ic0 = j << 5;
#pragma unroll
        for (int u = 0; u < 16; ++u)
            bv[u] = __ldg(xb + (size_t)(ic0 + kl + 2 * u) * HW + p0 + cl);
    };

    float bv[16], bv2[16];
    issueA(0);
    loadB(0, bv);

#pragma unroll 1
    for (int j = 0; j < 8; ++j) {
        const unsigned bo = (j & 1) * PWSTG;

        // transform + store B stage j (buffer j&1). Prior readers of this
        // buffer ran in iter j-2's compute, fenced by iter j-1's barrier.
        const int ic0 = j << 5;
#pragma unroll
        for (int u = 0; u < 16; ++u) {
            int kk = kl + 2 * u;
            int ic = ic0 + kk;
            float v = fmaxf(fmaf(bv[u], __ldg(&g_scale[ic]), __ldg(&g_shift[ic])), 0.f);
            unsigned hi = f2tf32(v);
            Bh[bo + kk * PASTR + cl] = hi;
            Bl[bo + kk * PASTR + cl] = f2tf32(v - __uint_as_float(hi));
        }

        asm volatile("cp.async.wait_group 0;" ::: "memory");   // A stage j landed
        __syncthreads();   // publishes B(j); all iter j-1 reads complete
        if (j < 7) {
            issueA(j + 1);     // buffer (j+1)&1: its readers finished pre-sync
            loadB(j + 1, bv2);
        }

#pragma unroll
        for (int ks = 0; ks < 32; ks += 8) {
            unsigned ah[4][4], al[4][4], bh[4][2], bl[4][2];
#pragma unroll
            for (int mi = 0; mi < 4; ++mi) {
                int oc = w_o + mi * 16 + gr;
                ah[mi][0] = Ah[bo + (ks + gc)     * PASTR + oc];
                ah[mi][1] = Ah[bo + (ks + gc)     * PASTR + oc + 8];
                ah[mi][2] = Ah[bo + (ks + gc + 4) * PASTR + oc];
                ah[mi][3] = Ah[bo + (ks + gc + 4) * PASTR + oc + 8];
                al[mi][0] = Al[bo + (ks + gc)     * PASTR + oc];
                al[mi][1] = Al[bo + (ks + gc)     * PASTR + oc + 8];
                al[mi][2] = Al[bo + (ks + gc + 4) * PASTR + oc];
                al[mi][3] = Al[bo + (ks + gc + 4) * PASTR + oc + 8];
            }
#pragma unroll
            for (int nj = 0; nj < 4; ++nj) {
                int pc = w_p + nj * 8 + gr;
                bh[nj][0] = Bh[bo + (ks + gc)     * PASTR + pc];
                bh[nj][1] = Bh[bo + (ks + gc + 4) * PASTR + pc];
                bl[nj][0] = Bl[bo + (ks + gc)     * PASTR + pc];
                bl[nj][1] = Bl[bo + (ks + gc + 4) * PASTR + pc];
            }
#define PW_MMA(AV, BV)                                                        \
    asm volatile(                                                             \
        "mma.sync.aligned.m16n8k8.row.col.f32.tf32.tf32.f32 "                 \
        "{%0,%1,%2,%3}, {%4,%5,%6,%7}, {%8,%9}, {%0,%1,%2,%3};"               \
        : "+f"(acc[mi][nj][0]), "+f"(acc[mi][nj][1]),                         \
          "+f"(acc[mi][nj][2]), "+f"(acc[mi][nj][3])                          \
        : "r"(AV[mi][0]), "r"(AV[mi][1]), "r"(AV[mi][2]), "r"(AV[mi][3]),     \
          "r"(BV[nj][0]), "r"(BV[nj][1]))
#pragma unroll
            for (int mi = 0; mi < 4; ++mi)
#pragma unroll
                for (int nj = 0; nj < 4; ++nj) {
                    PW_MMA(ah, bl);
                    PW_MMA(al, bh);
                    PW_MMA(ah, bh);
                }
#undef PW_MMA
        }

#pragma unroll
        for (int u = 0; u < 16; ++u) bv[u] = bv2[u];
    }

#pragma unroll
    for (int mi = 0; mi < 4; ++mi) {
#pragma unroll
        for (int nj = 0; nj < 4; ++nj) {
            int row0 = o0 + w_o + mi * 16 + gr;
            int col  = p0 + w_p + nj * 8 + 2 * gc;
            float* d0 = out + ((size_t)b * POUT + row0) * HW + col;
            float* d1 = d0 + 8 * HW;
            *(float2*)d0 = make_float2(acc[mi][nj][0], acc[mi][nj][1]);
            *(float2*)d1 = make_float2(acc[mi][nj][2], acc[mi][nj][3]);
        }
    }
}

// ---------------- launch -----------------------------------------------------
extern "C" void kernel_launch(void* const* d_in, const int* in_sizes, int n_in,
                              void* d_out, int out_size) {
    const float* x     = (const float*)d_in[0];
    const float* w_off = (const float*)d_in[1];
    const float* gamma = (const float*)d_in[2];
    const float* beta  = (const float*)d_in[3];
    const float* w_pw  = (const float*)d_in[4];
    float* out = (float*)d_out;

    static int smem_set = 0;
    const int dyn   = NSTG * STG * (int)sizeof(float);     // 204,800 B
    const int pwdyn = 8 * PWSTG * (int)sizeof(unsigned);   // 139,264 B
    if (!smem_set) {
        cudaFuncSetAttribute(k_offconv, cudaFuncAttributeMaxDynamicSharedMemorySize, dyn);
        cudaFuncSetAttribute(k_pw, cudaFuncAttributeMaxDynamicSharedMemorySize, pwdyn);
        smem_set = 1;
    }

    k_prep<<<(OC2 * C * 9 + 255) / 256, 256>>>(w_off, w_pw);
    k_prepx<<<BATCH * C * HW / 256, 256>>>(x);
    k_offconv<<<dim3((PP + 127) / 128, OC2 / 256, BATCH), 256, dyn>>>();
    k_sample<<<BATCH * C, 256>>>(x);
    k_bn<<<1, C>>>(gamma, beta);
    k_pw<<<dim3(HW / 128, POUT / 128, BATCH), 256, pwdyn>>>(out);
}

// round 16
// speedup vs baseline: 1.0599x; 1.0599x over previous
#include <cuda_runtime.h>
#include <cstdint>

#define BATCH 8
#define C 256
#define OC2 512
#define H 96
#define W 96
#define HW 9216          // 96*96
#define HP 98
#define PP 9604          // 98*98
#define POUT 256
#define EPS 1e-5f

// ---------------- scratch (static device globals; no allocation) -------------
__device__ float    g_wr[9 * C * OC2];       // conv weights [tap][ic][oc], tf32-rounded
__device__ float    g_xt[BATCH * C * HW];    // x, tf32-rounded (offconv B operand)
__device__ unsigned g_wpt_hi[C * POUT];      // pointwise weights tf32 [c][o]
__device__ float    g_off[(size_t)BATCH * OC2 * PP];
__device__ float    g_xd[BATCH * C * HW];
__device__ float    g_sums[2 * C];
__device__ float    g_scale[C];
__device__ float    g_shift[C];

__device__ __forceinline__ unsigned f2tf32(float f) {
    unsigned u;
    asm("cvt.rna.tf32.f32 %0, %1;" : "=r"(u) : "f"(f));
    return u;
}
__device__ __forceinline__ void cp16(unsigned dst, const void* src) {
    asm volatile("cp.async.cg.shared.global [%0], [%1], 16;"
                 :: "r"(dst), "l"(src));
}
__device__ __forceinline__ void cp4z(unsigned dst, const void* src, int srcsz) {
    asm volatile("cp.async.ca.shared.global [%0], [%1], 4, %2;"
                 :: "r"(dst), "l"(src), "r"(srcsz));
}

// ---------------- kernel 0: weight prep + stats re-zero ----------------------
__global__ void k_prep(const float* __restrict__ w, const float* __restrict__ wpw) {
    int i = blockIdx.x * 256 + threadIdx.x;
    if (i < 2 * C) g_sums[i] = 0.f;          // re-zero every call (graph replay)
    if (i < OC2 * C * 9) {
        int oc  = i / (C * 9);
        int r   = i - oc * (C * 9);
        int ic  = r / 9;
        int tap = r - ic * 9;
        g_wr[(tap * C + ic) * OC2 + oc] = __uint_as_float(f2tf32(w[i]));
    }
    if (i < POUT * C) {
        int o = i >> 8;      // POUT == 256
        int c = i & 255;     // C == 256
        g_wpt_hi[c * POUT + o] = f2tf32(wpw[i]);
    }
}

// ---------------- kernel 0b: pre-round x to tf32 -----------------------------
__global__ void k_prepx(const float* __restrict__ x) {
    int i = blockIdx.x * 256 + threadIdx.x;
    g_xt[i] = __uint_as_float(f2tf32(x[i]));
}

// ---------------- kernel 1: offset conv, TF32 mma.sync, BK=64 double-buffer --
// Block tile 256(oc) x 128(p). 256 threads = 8 warps (4 oc x 2 p), warp 64x64.
#define ASTR 264          // 256+8 floats
#define BSTR 136          // 128+8 floats
#define STG  (64 * ASTR + 64 * BSTR)   // floats per stage = 25600 (102.4 KB)
#define NSTG 2
#define NITER 36                        // 9 taps * 4 k-chunks of 64
__global__ __launch_bounds__(256, 1) void k_offconv() {
    extern __shared__ float sh[];      // NSTG * STG floats

    const int t    = threadIdx.x;
    const int warp = t >> 5;
    const int lane = t & 31;
    const int gr   = lane >> 2;
    const int gc   = lane & 3;
    const int w_oc = (warp >> 1) * 64;   // 0,64,128,192
    const int w_p  = (warp & 1) * 64;    // 0,64

    const int b   = blockIdx.z;
    const int oc0 = blockIdx.y * 256;
    const int p0  = blockIdx.x * 128;

    const int ppl = t & 127;
    const int kb  = t >> 7;             // 0..1
    const int P   = p0 + ppl;
    const bool pv = (P < PP);
    const int yy  = P / HP;
    const int xx  = P - yy * HP;

    float acc[4][8][4];
#pragma unroll
    for (int i = 0; i < 4; i++)
#pragma unroll
        for (int j = 0; j < 8; j++)
#pragma unroll
            for (int r = 0; r < 4; r++) acc[i][j][r] = 0.f;

    const float* xb = g_xt + (size_t)b * C * HW;

    auto issue = [&](int j) {
        const int s   = j & (NSTG - 1);
        const int tap = j >> 2;
        const int ic0 = (j & 3) << 6;
        float* stA = sh + s * STG;
        float* stB = stA + 64 * ASTR;
        {
            const float* wt = g_wr + (size_t)(tap * C + ic0) * OC2 + oc0;
#pragma unroll
            for (int u = 0; u < 16; ++u) {
                int c  = t + 256 * u;
                int ar = c >> 6;
                int ac = (c & 63) << 2;
                cp16((unsigned)__cvta_generic_to_shared(stA + ar * ASTR + ac),
                     wt + (size_t)ar * OC2 + ac);
            }
        }
        {
            const int ky = tap / 3;
            const int kx = tap - ky * 3;
            const int Y  = yy + ky - 2;
            const int X  = xx + kx - 2;
            const bool inb = pv && ((unsigned)Y < (unsigned)H) && ((unsigned)X < (unsigned)W);
            const int sp = inb ? (Y * W + X) : 0;
            const int sz = inb ? 4 : 0;
            const float* xc = xb + (size_t)ic0 * HW + sp;
#pragma unroll
            for (int u = 0; u < 32; ++u) {
                int kk = kb + 2 * u;
                cp4z((unsigned)__cvta_generic_to_shared(stB + kk * BSTR + ppl),
                     xc + (size_t)kk * HW, sz);
            }
        }
        asm volatile("cp.async.commit_group;" ::: "memory");
    };

    issue(0);

#pragma unroll 1
    for (int j = 0; j < NITER; ++j) {
        const int s = j & (NSTG - 1);
        asm volatile("cp.async.wait_group 0;" ::: "memory");   // stage j landed
        __syncthreads();
        if (j + 1 < NITER) issue(j + 1);

        const float* stA = sh + s * STG;
        const float* stB = stA + 64 * ASTR;

#pragma unroll
        for (int ks = 0; ks < 64; ks += 8) {
            unsigned af[4][4], bf[8][2];
#pragma unroll
            for (int mi = 0; mi < 4; ++mi) {
                int oc = w_oc + mi * 16 + gr;
                af[mi][0] = __float_as_uint(stA[(ks + gc)     * ASTR + oc]);
                af[mi][1] = __float_as_uint(stA[(ks + gc)     * ASTR + oc + 8]);
                af[mi][2] = __float_as_uint(stA[(ks + gc + 4) * ASTR + oc]);
                af[mi][3] = __float_as_uint(stA[(ks + gc + 4) * ASTR + oc + 8]);
            }
#pragma unroll
            for (int nj = 0; nj < 8; ++nj) {
                int pc = w_p + nj * 8 + gr;
                bf[nj][0] = __float_as_uint(stB[(ks + gc)     * BSTR + pc]);
                bf[nj][1] = __float_as_uint(stB[(ks + gc + 4) * BSTR + pc]);
            }
#pragma unroll
            for (int mi = 0; mi < 4; ++mi)
#pragma unroll
                for (int nj = 0; nj < 8; ++nj)
                    asm volatile(
                        "mma.sync.aligned.m16n8k8.row.col.f32.tf32.tf32.f32 "
                        "{%0,%1,%2,%3}, {%4,%5,%6,%7}, {%8,%9}, {%0,%1,%2,%3};"
                        : "+f"(acc[mi][nj][0]), "+f"(acc[mi][nj][1]),
                          "+f"(acc[mi][nj][2]), "+f"(acc[mi][nj][3])
                        : "r"(af[mi][0]), "r"(af[mi][1]), "r"(af[mi][2]), "r"(af[mi][3]),
                          "r"(bf[nj][0]), "r"(bf[nj][1]));
        }
    }

#pragma unroll
    for (int mi = 0; mi < 4; ++mi) {
#pragma unroll
        for (int nj = 0; nj < 8; ++nj) {
            int row0 = oc0 + w_oc + mi * 16 + gr;
            int col  = p0 + w_p + nj * 8 + 2 * gc;
            float* d0 = g_off + ((size_t)b * OC2 + row0) * PP + col;
            float* d1 = d0 + 8 * PP;
            if (col + 1 < PP) {
                *(float2*)d0 = make_float2(acc[mi][nj][0], acc[mi][nj][1]);
                *(float2*)d1 = make_float2(acc[mi][nj][2], acc[mi][nj][3]);
            } else if (col < PP) {
                d0[0] = acc[mi][nj][0];
                d1[0] = acc[mi][nj][2];
            }
        }
    }
}

// ---------------- kernel 2: bilinear deform sampling + BN partial sums -------
__global__ __launch_bounds__(256) void k_sample(const float* __restrict__ x) {
    const int bc = blockIdx.x;
    const int b  = bc >> 8;
    const int c  = bc & 255;
    const float* xc = x + (size_t)bc * HW;
    const float* offb = g_off + ((size_t)b * OC2 + 2 * c) * PP;

    float s1 = 0.f, s2 = 0.f;
    for (int i = threadIdx.x; i < HW; i += 256) {
        int iy = i / W;
        int ix = i - iy * W;
        int yy = iy + 1, xx = ix + 1;
        int p2 = 2 * (yy * HP + xx);
        float oy = __ldg(offb + p2);
        float ox = __ldg(offb + p2 + 1);
        float cy = fminf(fmaxf((float)yy + oy, 0.f), 97.f);
        float cx = fminf(fmaxf((float)xx + ox, 0.f), 97.f);
        float fy = floorf(cy), fx = floorf(cx);
        int y0 = (int)fy, x0 = (int)fx;
        int y1 = min(y0 + 1, 97), x1 = min(x0 + 1, 97);
        float dy = cy - fy, dx = cx - fx;
        float v00 = (y0 >= 1 && y0 <= 96 && x0 >= 1 && x0 <= 96) ? __ldg(xc + (y0 - 1) * W + (x0 - 1)) : 0.f;
        float v01 = (y0 >= 1 && y0 <= 96 && x1 >= 1 && x1 <= 96) ? __ldg(xc + (y0 - 1) * W + (x1 - 1)) : 0.f;
        float v10 = (y1 >= 1 && y1 <= 96 && x0 >= 1 && x0 <= 96) ? __ldg(xc + (y1 - 1) * W + (x0 - 1)) : 0.f;
        float v11 = (y1 >= 1 && y1 <= 96 && x1 >= 1 && x1 <= 96) ? __ldg(xc + (y1 - 1) * W + (x1 - 1)) : 0.f;
        float top = v00 + (v01 - v00) * dx;
        float bot = v10 + (v11 - v10) * dx;
        float v   = top + (bot - top) * dy;
        g_xd[(size_t)bc * HW + i] = v;
        s1 += v;
        s2 += v * v;
    }
#pragma unroll
    for (int off = 16; off > 0; off >>= 1) {
        s1 += __shfl_down_sync(0xffffffffu, s1, off);
        s2 += __shfl_down_sync(0xffffffffu, s2, off);
    }
    __shared__ float r1[8], r2[8];
    int lane = threadIdx.x & 31, wid = threadIdx.x >> 5;
    if (lane == 0) { r1[wid] = s1; r2[wid] = s2; }
    __syncthreads();
    if (threadIdx.x == 0) {
        float a = 0.f, q = 0.f;
#pragma unroll
        for (int i = 0; i < 8; i++) { a += r1[i]; q += r2[i]; }
        atomicAdd(&g_sums[2 * c], a);
        atomicAdd(&g_sums[2 * c + 1], q);
    }
}

// ---------------- kernel 3: BN scale/shift from batch stats ------------------
__global__ void k_bn(const float* __restrict__ gamma, const float* __restrict__ beta) {
    int c = threadIdx.x;
    const float invn = 1.f / (float)(BATCH * HW);
    float mean = g_sums[2 * c] * invn;
    float var  = g_sums[2 * c + 1] * invn - mean * mean;
    float inv  = rsqrtf(var + EPS);
    float sc   = gamma[c] * inv;
    g_scale[c] = sc;
    g_shift[c] = fmaf(-mean, sc, beta[c]);
}

// ---------------- kernel 4: pointwise 1x1, single-pass TF32 mma, pipelined ---
// Block tile 128(o) x 128(p), BK=32, 8 k-iters. 256 threads = 8 warps (2x4).
// Order per iter: store-B(j) -> wait_group 0 -> sync -> issueA(j+1) -> loadB(j+1)
// -> compute(j). Single tf32 term (no hi/lo split): 1/3 the MMAs, half smem.
#define PASTR 136
#define PWSTG (32 * PASTR)              // words per plane per buffer = 4352
__global__ __launch_bounds__(256) void k_pw(float* __restrict__ out) {
    extern __shared__ unsigned psh[];   // Ah[2] | Bh[2]
    unsigned* Ah = psh;
    unsigned* Bh = psh + 2 * PWSTG;

    const int t    = threadIdx.x;
    const int warp = t >> 5;
    const int lane = t & 31;
    const int gr   = lane >> 2;
    const int gc   = lane & 3;
    const int w_o  = (warp >> 2) * 64;
    const int w_p  = (warp & 3) * 32;

    const int b  = blockIdx.z;
    const int o0 = blockIdx.y * 128;
    const int p0 = blockIdx.x * 128;

    const int cl = t & 127;   // B loader column
    const int kl = t >> 7;    // B loader row base (0..1)

    const float* xb = g_xd + (size_t)b * C * HW;

    float acc[4][4][4];
#pragma unroll
    for (int i = 0; i < 4; i++)
#pragma unroll
        for (int j = 0; j < 4; j++)
#pragma unroll
            for (int r = 0; r < 4; r++) acc[i][j][r] = 0.f;

    // A stage loader: 32 rows x 128 cols, 4 cp16 per thread
    auto issueA = [&](int j) {
        const int ic0 = j << 5;
        const unsigned bo = (j & 1) * PWSTG;
        const unsigned* wh = g_wpt_hi + (size_t)ic0 * POUT + o0;
#pragma unroll
        for (int u = 0; u < 4; ++u) {
            int id = t + 256 * u;        // 0..1023
            int r  = id >> 5;            // 0..31
            int c4 = (id & 31) << 2;     // 0..124
            cp16((unsigned)__cvta_generic_to_shared(Ah + bo + r * PASTR + c4),
                 wh + (size_t)r * POUT + c4);
        }
        asm volatile("cp.async.commit_group;" ::: "memory");
    };
    // B prefetch: 16 raw values into registers
    auto loadB = [&](int j, float* bv) {
        const int ic0 = j << 5;
#pragma unroll
        for (int u = 0; u < 16; ++u)
            bv[u] = __ldg(xb + (size_t)(ic0 + kl + 2 * u) * HW + p0 + cl);
    };

    float bv[16], bv2[16];
    issueA(0);
    loadB(0, bv);

#pragma unroll 1
    for (int j = 0; j < 8; ++j) {
        const unsigned bo = (j & 1) * PWSTG;

        // transform + store B stage j (BN + ReLU + tf32 round)
        const int ic0 = j << 5;
#pragma unroll
        for (int u = 0; u < 16; ++u) {
            int kk = kl + 2 * u;
            int ic = ic0 + kk;
            float v = fmaxf(fmaf(bv[u], __ldg(&g_scale[ic]), __ldg(&g_shift[ic])), 0.f);
            Bh[bo + kk * PASTR + cl] = f2tf32(v);
        }

        asm volatile("cp.async.wait_group 0;" ::: "memory");   // A stage j landed
        __syncthreads();   // publishes B(j); all iter j-1 reads complete
        if (j < 7) {
            issueA(j + 1);     // buffer (j+1)&1: its readers finished pre-sync
            loadB(j + 1, bv2);
        }

#pragma unroll
        for (int ks = 0; ks < 32; ks += 8) {
            unsigned ah[4][4], bh[4][2];
#pragma unroll
            for (int mi = 0; mi < 4; ++mi) {
                int oc = w_o + mi * 16 + gr;
                ah[mi][0] = Ah[bo + (ks + gc)     * PASTR + oc];
                ah[mi][1] = Ah[bo + (ks + gc)     * PASTR + oc + 8];
                ah[mi][2] = Ah[bo + (ks + gc + 4) * PASTR + oc];
                ah[mi][3] = Ah[bo + (ks + gc + 4) * PASTR + oc + 8];
            }
#pragma unroll
            for (int nj = 0; nj < 4; ++nj) {
                int pc = w_p + nj * 8 + gr;
                bh[nj][0] = Bh[bo + (ks + gc)     * PASTR + pc];
                bh[nj][1] = Bh[bo + (ks + gc + 4) * PASTR + pc];
            }
#pragma unroll
            for (int mi = 0; mi < 4; ++mi)
#pragma unroll
                for (int nj = 0; nj < 4; ++nj)
                    asm volatile(
                        "mma.sync.aligned.m16n8k8.row.col.f32.tf32.tf32.f32 "
                        "{%0,%1,%2,%3}, {%4,%5,%6,%7}, {%8,%9}, {%0,%1,%2,%3};"
                        : "+f"(acc[mi][nj][0]), "+f"(acc[mi][nj][1]),
                          "+f"(acc[mi][nj][2]), "+f"(acc[mi][nj][3])
                        : "r"(ah[mi][0]), "r"(ah[mi][1]), "r"(ah[mi][2]), "r"(ah[mi][3]),
                          "r"(bh[nj][0]), "r"(bh[nj][1]));
        }

#pragma unroll
        for (int u = 0; u < 16; ++u) bv[u] = bv2[u];
    }

#pragma unroll
    for (int mi = 0; mi < 4; ++mi) {
#pragma unroll
        for (int nj = 0; nj < 4; ++nj) {
            int row0 = o0 + w_o + mi * 16 + gr;
            int col  = p0 + w_p + nj * 8 + 2 * gc;
            float* d0 = out + ((size_t)b * POUT + row0) * HW + col;
            float* d1 = d0 + 8 * HW;
            *(float2*)d0 = make_float2(acc[mi][nj][0], acc[mi][nj][1]);
            *(float2*)d1 = make_float2(acc[mi][nj][2], acc[mi][nj][3]);
        }
    }
}

// ---------------- launch -----------------------------------------------------
extern "C" void kernel_launch(void* const* d_in, const int* in_sizes, int n_in,
                              void* d_out, int out_size) {
    const float* x     = (const float*)d_in[0];
    const float* w_off = (const float*)d_in[1];
    const float* gamma = (const float*)d_in[2];
    const float* beta  = (const float*)d_in[3];
    const float* w_pw  = (const float*)d_in[4];
    float* out = (float*)d_out;

    static int smem_set = 0;
    const int dyn   = NSTG * STG * (int)sizeof(float);     // 204,800 B
    const int pwdyn = 4 * PWSTG * (int)sizeof(unsigned);   // 69,632 B
    if (!smem_set) {
        cudaFuncSetAttribute(k_offconv, cudaFuncAttributeMaxDynamicSharedMemorySize, dyn);
        cudaFuncSetAttribute(k_pw, cudaFuncAttributeMaxDynamicSharedMemorySize, pwdyn);
        smem_set = 1;
    }

    k_prep<<<(OC2 * C * 9 + 255) / 256, 256>>>(w_off, w_pw);
    k_prepx<<<BATCH * C * HW / 256, 256>>>(x);
    k_offconv<<<dim3((PP + 127) / 128, OC2 / 256, BATCH), 256, dyn>>>();
    k_sample<<<BATCH * C, 256>>>(x);
    k_bn<<<1, C>>>(gamma, beta);
    k_pw<<<dim3(HW / 128, POUT / 128, BATCH), 256, pwdyn>>>(out);
}